// round 3
// baseline (speedup 1.0000x reference)
#include <cuda_runtime.h>
#include <math.h>

#define MAXN 100000
#define NS 16
#define C 64
#define WPB 4          // warps (= points) per block

// Scratch for Q/K/V projections (allocation-free rule: __device__ globals)
__device__ float g_q[MAXN * C];
__device__ float g_k[MAXN * C];
__device__ float g_v[MAXN * C];

typedef unsigned long long ull;

__device__ __forceinline__ ull pack2(float x, float y) {
    ull d; asm("mov.b64 %0, {%1, %2};" : "=l"(d) : "f"(x), "f"(y)); return d;
}
__device__ __forceinline__ void unpack2(ull d, float& x, float& y) {
    asm("mov.b64 {%0, %1}, %2;" : "=f"(x), "=f"(y) : "l"(d));
}
__device__ __forceinline__ ull fma2(ull a, ull b, ull c) {
    ull d; asm("fma.rn.f32x2 %0, %1, %2, %3;" : "=l"(d) : "l"(a), "l"(b), "l"(c)); return d;
}

// ---------------------------------------------------------------------------
// Kernel 1: QKV projection with packed f32x2 FMA. grid=(ceil(N/64),3), 256 thr.
// ---------------------------------------------------------------------------
__global__ void __launch_bounds__(256) qkv_gemm(
    const float* __restrict__ x,
    const float* __restrict__ Wq, const float* __restrict__ bq,
    const float* __restrict__ Wk, const float* __restrict__ bk,
    const float* __restrict__ Wv, const float* __restrict__ bv,
    int N)
{
    __shared__ float xs[64][68];
    __shared__ float ws[64][64];

    const float* W;
    const float* b;
    float* out;
    if (blockIdx.y == 0)      { W = Wq; b = bq; out = g_q; }
    else if (blockIdx.y == 1) { W = Wk; b = bk; out = g_k; }
    else                      { W = Wv; b = bv; out = g_v; }

    const int r0  = blockIdx.x * 64;
    const int tid = threadIdx.x;

    #pragma unroll
    for (int t = 0; t < 4; t++) {
        int i4  = tid + 256 * t;
        int row = i4 >> 4;
        int c4  = (i4 & 15) << 2;
        float4 wv4 = *(const float4*)(W + row * 64 + c4);
        *(float4*)(&ws[row][c4]) = wv4;
        int gr = r0 + row;
        float4 xv4 = (gr < N) ? *(const float4*)(x + (long long)gr * 64 + c4)
                              : make_float4(0.f, 0.f, 0.f, 0.f);
        *(float4*)(&xs[row][c4]) = xv4;
    }
    __syncthreads();

    const int tx = tid & 15;
    const int ty = tid >> 4;

    float4 bias4 = *(const float4*)(b + tx * 4);
    ull acc2[4][2];
    #pragma unroll
    for (int r = 0; r < 4; r++) {
        acc2[r][0] = pack2(bias4.x, bias4.y);
        acc2[r][1] = pack2(bias4.z, bias4.w);
    }

    #pragma unroll 8
    for (int k = 0; k < 64; k++) {
        float4 w4 = *(const float4*)(&ws[k][tx * 4]);
        ull w01 = pack2(w4.x, w4.y);
        ull w23 = pack2(w4.z, w4.w);
        #pragma unroll
        for (int r = 0; r < 4; r++) {
            float a = xs[ty * 4 + r][k];
            ull ad = pack2(a, a);
            acc2[r][0] = fma2(ad, w01, acc2[r][0]);
            acc2[r][1] = fma2(ad, w23, acc2[r][1]);
        }
    }

    #pragma unroll
    for (int r = 0; r < 4; r++) {
        int gr = r0 + ty * 4 + r;
        if (gr < N) {
            float4 o4;
            unpack2(acc2[r][0], o4.x, o4.y);
            unpack2(acc2[r][1], o4.z, o4.w);
            *(float4*)(out + (long long)gr * 64 + tx * 4) = o4;
        }
    }
}

// ---------------------------------------------------------------------------
// Kernel 2: warp-per-point attention. Block = 128 thr = 4 warps = 4 points.
// Lane = jj*2 + half: neighbor jj (0..15), channel half (32 channels each).
// No __syncthreads in hot path; one __syncwarp per point.
// ---------------------------------------------------------------------------
__global__ void __launch_bounds__(128) pt_attn(
    const float* __restrict__ p,
    const int*   __restrict__ idx,
    const float* __restrict__ Wp1, const float* __restrict__ bp1,
    const float* __restrict__ gp,  const float* __restrict__ bpv,
    const float* __restrict__ Wp2, const float* __restrict__ bp2,
    const float* __restrict__ g1,  const float* __restrict__ bb1,
    const float* __restrict__ Wa,  const float* __restrict__ ba,
    const float* __restrict__ g2,  const float* __restrict__ bb2,
    const float* __restrict__ Wb,  const float* __restrict__ bw,
    float* __restrict__ out, int N)
{
    const int tid  = threadIdx.x;
    const int wid  = tid >> 5;
    const int lane = tid & 31;
    const int jj   = lane >> 1;
    const int half = lane & 1;

    __shared__ float4 s_pew[64];        // {Wp2[0][c], Wp2[1][c], Wp2[2][c], bp2[c]}
    __shared__ float2 s_s1b1[64];       // {g1*binv, bb1}
    __shared__ float  s_Wa[64][8];      // row-major [c][ch]
    __shared__ float  s_Wbt[8][8];      // Wbt[l][ch] = Wb[ch][l]
    __shared__ float  s_misc[64];       // 0:ba 8:s2 16:b2 24:bw 32:Wp1(9) 41:bp1 44:gp*binv 47:bp
    __shared__ float  s_val[WPB][16][68];
    __shared__ float  s_w[WPB][16][8];

    const float bninv = rsqrtf(1.f + 1e-5f);

    if (tid < 64) {
        s_pew[tid]  = make_float4(__ldg(Wp2 + tid), __ldg(Wp2 + 64 + tid),
                                  __ldg(Wp2 + 128 + tid), __ldg(bp2 + tid));
        s_s1b1[tid] = make_float2(__ldg(g1 + tid) * bninv, __ldg(bb1 + tid));
        s_Wbt[tid & 7][tid >> 3] = __ldg(Wb + tid);
    }
    for (int t = tid; t < 512; t += 128) s_Wa[t >> 3][t & 7] = __ldg(Wa + t);
    if (tid < 8) {
        s_misc[tid]      = __ldg(ba + tid);
        s_misc[8 + tid]  = __ldg(g2 + tid) * bninv;
        s_misc[16 + tid] = __ldg(bb2 + tid);
        s_misc[24 + tid] = __ldg(bw + tid);
    }
    if (tid < 9)  s_misc[32 + tid] = __ldg(Wp1 + tid);
    if (tid < 3) {
        s_misc[41 + tid] = __ldg(bp1 + tid);
        s_misc[44 + tid] = __ldg(gp + tid) * bninv;
        s_misc[47 + tid] = __ldg(bpv + tid);
    }
    __syncthreads();

    const int i = blockIdx.x * WPB + wid;
    if (i >= N) return;                 // uniform per warp

    // relative position + positional-MLP hidden (per jj, both halves redundant)
    const int nj = __ldg(idx + i * NS + jj);
    const float rx = __ldg(p + nj * 3 + 0) - __ldg(p + i * 3 + 0);
    const float ry = __ldg(p + nj * 3 + 1) - __ldg(p + i * 3 + 1);
    const float rz = __ldg(p + nj * 3 + 2) - __ldg(p + i * 3 + 2);
    float t3[3];
    #pragma unroll
    for (int o = 0; o < 3; o++) {
        float u = fmaf(rx, s_misc[32 + o],
                  fmaf(ry, s_misc[35 + o],
                  fmaf(rz, s_misc[38 + o], s_misc[41 + o])));
        t3[o] = fmaxf(fmaf(u, s_misc[44 + o], s_misc[47 + o]), 0.f);
    }

    const int cb = half * 32;
    const float* qrow = g_q + (long long)i  * 64 + cb;
    const float* krow = g_k + (long long)nj * 64 + cb;
    const float* vrow = g_v + (long long)nj * 64 + cb;
    float* svrow = &s_val[wid][jj][cb];

    ull acc2[4] = {0ull, 0ull, 0ull, 0ull};   // y[0..7] packed pairs

    #pragma unroll
    for (int g = 0; g < 8; g++) {
        const int c0 = cb + g * 4;
        float4 q4 = *(const float4*)(qrow + g * 4);
        float4 k4 = *(const float4*)(krow + g * 4);
        float4 v4 = *(const float4*)(vrow + g * 4);
        float4 pw0 = s_pew[c0 + 0], pw1 = s_pew[c0 + 1];
        float4 pw2 = s_pew[c0 + 2], pw3 = s_pew[c0 + 3];

        float pe0 = fmaf(t3[0], pw0.x, fmaf(t3[1], pw0.y, fmaf(t3[2], pw0.z, pw0.w)));
        float pe1 = fmaf(t3[0], pw1.x, fmaf(t3[1], pw1.y, fmaf(t3[2], pw1.z, pw1.w)));
        float pe2 = fmaf(t3[0], pw2.x, fmaf(t3[1], pw2.y, fmaf(t3[2], pw2.z, pw2.w)));
        float pe3 = fmaf(t3[0], pw3.x, fmaf(t3[1], pw3.y, fmaf(t3[2], pw3.z, pw3.w)));

        // value + pe (pre-weight) -> smem
        *(float4*)(svrow + g * 4) =
            make_float4(v4.x + pe0, v4.y + pe1, v4.z + pe2, v4.w + pe3);

        float2 sb0 = s_s1b1[c0 + 0], sb1 = s_s1b1[c0 + 1];
        float2 sb2 = s_s1b1[c0 + 2], sb3 = s_s1b1[c0 + 3];
        float wv0 = fmaxf(fmaf(k4.x - q4.x + pe0, sb0.x, sb0.y), 0.f);
        float wv1 = fmaxf(fmaf(k4.y - q4.y + pe1, sb1.x, sb1.y), 0.f);
        float wv2 = fmaxf(fmaf(k4.z - q4.z + pe2, sb2.x, sb2.y), 0.f);
        float wv3 = fmaxf(fmaf(k4.w - q4.w + pe3, sb3.x, sb3.y), 0.f);

        // y[ch] += wv_c * Wa[c][ch], packed pairs (broadcast smem reads)
        #pragma unroll
        for (int m = 0; m < 4; m++) {
            float wvm = (m == 0) ? wv0 : (m == 1) ? wv1 : (m == 2) ? wv2 : wv3;
            float4 wa01 = *(const float4*)&s_Wa[c0 + m][0];
            float4 wa23 = *(const float4*)&s_Wa[c0 + m][4];
            ull wd = pack2(wvm, wvm);
            acc2[0] = fma2(wd, pack2(wa01.x, wa01.y), acc2[0]);
            acc2[1] = fma2(wd, pack2(wa01.z, wa01.w), acc2[1]);
            acc2[2] = fma2(wd, pack2(wa23.x, wa23.y), acc2[2]);
            acc2[3] = fma2(wd, pack2(wa23.z, wa23.w), acc2[3]);
        }
    }

    // combine the two halves' partial y
    float acc[8];
    unpack2(acc2[0], acc[0], acc[1]);
    unpack2(acc2[1], acc[2], acc[3]);
    unpack2(acc2[2], acc[4], acc[5]);
    unpack2(acc2[3], acc[6], acc[7]);
    #pragma unroll
    for (int t = 0; t < 8; t++)
        acc[t] += __shfl_xor_sync(0xffffffffu, acc[t], 1);

    // BN2 + ReLU
    float a[8];
    #pragma unroll
    for (int ch = 0; ch < 8; ch++)
        a[ch] = fmaxf(fmaf(acc[ch] + s_misc[ch], s_misc[8 + ch], s_misc[16 + ch]), 0.f);

    // scores for l = half*4 + q
    float sc[4];
    #pragma unroll
    for (int q = 0; q < 4; q++) {
        const int l = half * 4 + q;
        float4 b0 = *(const float4*)&s_Wbt[l][0];
        float4 b1 = *(const float4*)&s_Wbt[l][4];
        float s = s_misc[24 + l];
        s = fmaf(a[0], b0.x, s); s = fmaf(a[1], b0.y, s);
        s = fmaf(a[2], b0.z, s); s = fmaf(a[3], b0.w, s);
        s = fmaf(a[4], b1.x, s); s = fmaf(a[5], b1.y, s);
        s = fmaf(a[6], b1.z, s); s = fmaf(a[7], b1.w, s);
        sc[q] = s;
    }

    // softmax over jj (xor over bits 1..4 keeps half fixed, reduces over all 16 jj)
    float mx[4] = {sc[0], sc[1], sc[2], sc[3]};
    #pragma unroll
    for (int off = 2; off <= 16; off <<= 1) {
        #pragma unroll
        for (int q = 0; q < 4; q++)
            mx[q] = fmaxf(mx[q], __shfl_xor_sync(0xffffffffu, mx[q], off));
    }
    float ex[4], sm[4];
    #pragma unroll
    for (int q = 0; q < 4; q++) { ex[q] = __expf(sc[q] - mx[q]); sm[q] = ex[q]; }
    #pragma unroll
    for (int off = 2; off <= 16; off <<= 1) {
        #pragma unroll
        for (int q = 0; q < 4; q++)
            sm[q] += __shfl_xor_sync(0xffffffffu, sm[q], off);
    }
    float4 wq = make_float4(ex[0] / sm[0], ex[1] / sm[1], ex[2] / sm[2], ex[3] / sm[3]);
    *(float4*)&s_w[wid][jj][half * 4] = wq;
    __syncwarp();

    // aggregation: lane pair (jj,*) sums channel group jj*4..+4 over all 16 j.
    // w index for channel u = jj*4+m is u&7 = (jj&1)*4 + m.
    const int lsel = (jj & 1) * 4;
    float4 o = make_float4(0.f, 0.f, 0.f, 0.f);
    #pragma unroll
    for (int j2 = 0; j2 < 16; j2++) {
        float4 v4 = *(const float4*)&s_val[wid][j2][jj * 4];
        float4 w4 = *(const float4*)&s_w[wid][j2][lsel];
        o.x = fmaf(v4.x, w4.x, o.x); o.y = fmaf(v4.y, w4.y, o.y);
        o.z = fmaf(v4.z, w4.z, o.z); o.w = fmaf(v4.w, w4.w, o.w);
    }
    if (half == 0)
        *(float2*)(out + (long long)i * 64 + jj * 4)     = make_float2(o.x, o.y);
    else
        *(float2*)(out + (long long)i * 64 + jj * 4 + 2) = make_float2(o.z, o.w);
}

// ---------------------------------------------------------------------------
extern "C" void kernel_launch(void* const* d_in, const int* in_sizes, int n_in,
                              void* d_out, int out_size)
{
    const float* p   = (const float*)d_in[0];
    const float* x   = (const float*)d_in[1];
    const int*   idx = (const int*)  d_in[2];
    const float* Wq  = (const float*)d_in[3];
    const float* bq  = (const float*)d_in[4];
    const float* Wk  = (const float*)d_in[5];
    const float* bk  = (const float*)d_in[6];
    const float* Wv  = (const float*)d_in[7];
    const float* bv  = (const float*)d_in[8];
    const float* Wp1 = (const float*)d_in[9];
    const float* bp1 = (const float*)d_in[10];
    const float* gp  = (const float*)d_in[11];
    const float* bpv = (const float*)d_in[12];
    const float* Wp2 = (const float*)d_in[13];
    const float* bp2 = (const float*)d_in[14];
    const float* g1  = (const float*)d_in[15];
    const float* bb1 = (const float*)d_in[16];
    const float* Wa  = (const float*)d_in[17];
    const float* ba  = (const float*)d_in[18];
    const float* g2  = (const float*)d_in[19];
    const float* bb2 = (const float*)d_in[20];
    const float* Wb  = (const float*)d_in[21];
    const float* bw  = (const float*)d_in[22];
    float* out = (float*)d_out;

    int N = in_sizes[1] / C;
    if (N > MAXN) N = MAXN;

    dim3 gridA((N + 63) / 64, 3);
    qkv_gemm<<<gridA, 256>>>(x, Wq, bq, Wk, bk, Wv, bv, N);

    pt_attn<<<(N + WPB - 1) / WPB, 128>>>(p, idx, Wp1, bp1, gp, bpv, Wp2, bp2,
                                          g1, bb1, Wa, ba, g2, bb2, Wb, bw, out, N);
}

// round 4
// speedup vs baseline: 1.2368x; 1.2368x over previous
#include <cuda_runtime.h>
#include <math.h>

#define MAXN 100000
#define NS 16
#define C 64
#define PTS 8          // points per block (sequential)
#define QROWS 128      // rows per qkv block

// Scratch for Q/K/V projections (allocation-free rule: __device__ globals)
__device__ float g_q[MAXN * C];
__device__ float g_k[MAXN * C];
__device__ float g_v[MAXN * C];

typedef unsigned long long ull;

__device__ __forceinline__ ull pack2(float x, float y) {
    ull d; asm("mov.b64 %0, {%1, %2};" : "=l"(d) : "f"(x), "f"(y)); return d;
}
__device__ __forceinline__ void unpack2(ull d, float& x, float& y) {
    asm("mov.b64 {%0, %1}, %2;" : "=f"(x), "=f"(y) : "l"(d));
}
__device__ __forceinline__ ull fma2(ull a, ull b, ull c) {
    ull d; asm("fma.rn.f32x2 %0, %1, %2, %3;" : "=l"(d) : "l"(a), "l"(b), "l"(c)); return d;
}

// ---------------------------------------------------------------------------
// Kernel 1: fused QKV projection. One block: 128 rows, all 3 weight sets.
// 8x8 register tiling, x transposed in smem, packed f32x2 FMA.
// ---------------------------------------------------------------------------
__global__ void __launch_bounds__(128) qkv_gemm(
    const float* __restrict__ x,
    const float* __restrict__ Wq, const float* __restrict__ bq,
    const float* __restrict__ Wk, const float* __restrict__ bk,
    const float* __restrict__ Wv, const float* __restrict__ bv,
    int N)
{
    __shared__ float xsT[64][132];
    __shared__ float ws[64][68];

    const int tid = threadIdx.x;
    const int r0  = blockIdx.x * QROWS;

    // Load x rows transposed into xsT[k][row]
    {
        const int r = r0 + tid;
        if (r < N) {
            const float4* xr = (const float4*)(x + (long long)r * 64);
            #pragma unroll
            for (int f = 0; f < 16; f++) {
                float4 v = __ldg(xr + f);
                xsT[f * 4 + 0][tid] = v.x;
                xsT[f * 4 + 1][tid] = v.y;
                xsT[f * 4 + 2][tid] = v.z;
                xsT[f * 4 + 3][tid] = v.w;
            }
        } else {
            #pragma unroll
            for (int f = 0; f < 16; f++) {
                xsT[f * 4 + 0][tid] = 0.f; xsT[f * 4 + 1][tid] = 0.f;
                xsT[f * 4 + 2][tid] = 0.f; xsT[f * 4 + 3][tid] = 0.f;
            }
        }
    }

    const int tx = tid & 7;     // col group: cols tx*8 .. tx*8+7
    const int ty = tid >> 3;    // row group: rows ty*8 .. ty*8+7

    #pragma unroll 1
    for (int s = 0; s < 3; s++) {
        const float* W = (s == 0) ? Wq : (s == 1) ? Wk : Wv;
        const float* b = (s == 0) ? bq : (s == 1) ? bk : bv;
        float* outp    = (s == 0) ? g_q : (s == 1) ? g_k : g_v;

        __syncthreads();
        #pragma unroll
        for (int u = 0; u < 8; u++) {
            int i4  = tid + 128 * u;          // 0..1023 float4 index
            int row = i4 >> 4;
            int c4  = (i4 & 15) << 2;
            *(float4*)&ws[row][c4] = __ldg((const float4*)(W + row * 64 + c4));
        }
        __syncthreads();

        float4 bA = __ldg((const float4*)(b + tx * 8));
        float4 bB = __ldg((const float4*)(b + tx * 8 + 4));
        ull acc[8][4];
        #pragma unroll
        for (int r = 0; r < 8; r++) {
            acc[r][0] = pack2(bA.x, bA.y);
            acc[r][1] = pack2(bA.z, bA.w);
            acc[r][2] = pack2(bB.x, bB.y);
            acc[r][3] = pack2(bB.z, bB.w);
        }

        #pragma unroll 4
        for (int k = 0; k < 64; k++) {
            float4 xa = *(const float4*)&xsT[k][ty * 8];
            float4 xb = *(const float4*)&xsT[k][ty * 8 + 4];
            float4 wa = *(const float4*)&ws[k][tx * 8];
            float4 wb = *(const float4*)&ws[k][tx * 8 + 4];
            ull w0 = pack2(wa.x, wa.y), w1 = pack2(wa.z, wa.w);
            ull w2 = pack2(wb.x, wb.y), w3 = pack2(wb.z, wb.w);
            float xr[8] = {xa.x, xa.y, xa.z, xa.w, xb.x, xb.y, xb.z, xb.w};
            #pragma unroll
            for (int r = 0; r < 8; r++) {
                ull ad = pack2(xr[r], xr[r]);
                acc[r][0] = fma2(ad, w0, acc[r][0]);
                acc[r][1] = fma2(ad, w1, acc[r][1]);
                acc[r][2] = fma2(ad, w2, acc[r][2]);
                acc[r][3] = fma2(ad, w3, acc[r][3]);
            }
        }

        #pragma unroll
        for (int r = 0; r < 8; r++) {
            int gr = r0 + ty * 8 + r;
            if (gr < N) {
                float4 o1, o2;
                unpack2(acc[r][0], o1.x, o1.y);
                unpack2(acc[r][1], o1.z, o1.w);
                unpack2(acc[r][2], o2.x, o2.y);
                unpack2(acc[r][3], o2.z, o2.w);
                float* op = outp + (long long)gr * 64 + tx * 8;
                *(float4*)op       = o1;
                *(float4*)(op + 4) = o2;
            }
        }
    }
}

// ---------------------------------------------------------------------------
// Kernel 2: per-point attention. 128 threads, PTS points sequential.
// Thread (j = tid>>3, l = tid&7): neighbor j, channels {h*32 + l*4 + m}.
// wv and val stay in registers; only scores/weights/partials touch smem.
// ---------------------------------------------------------------------------
__global__ void __launch_bounds__(128) pt_attn(
    const float* __restrict__ p,
    const int*   __restrict__ idx,
    const float* __restrict__ Wp1, const float* __restrict__ bp1,
    const float* __restrict__ gp,  const float* __restrict__ bpv,
    const float* __restrict__ Wp2, const float* __restrict__ bp2,
    const float* __restrict__ g1,  const float* __restrict__ bb1,
    const float* __restrict__ Wa,  const float* __restrict__ ba,
    const float* __restrict__ g2,  const float* __restrict__ bb2,
    const float* __restrict__ Wb,  const float* __restrict__ bw,
    float* __restrict__ out, int N)
{
    const int tid = threadIdx.x;
    const int wid = tid >> 5;
    const int j   = tid >> 3;     // 0..15
    const int l   = tid & 7;

    __shared__ float  s_Wat[8][68];    // Wa^T [ch][c]
    __shared__ float  s_Wbt[8][12];    // Wb^T [lout][ch]
    __shared__ float  s_Wp2s[3][68];
    __shared__ float  s_bp2[64];
    __shared__ float2 s_s1b1[64];      // {g1*binv, bb1}
    __shared__ float  s_misc[64];      // 0:ba 8:s2 16:b2 24:bw 32:Wp1(9) 41:bp1 44:gp*binv 47:bp
    __shared__ float  s_wraw[16][12];
    __shared__ float  s_w[16][8];
    __shared__ float  s_part[4][68];

    const float bninv = rsqrtf(1.f + 1e-5f);

    for (int t = tid; t < 512; t += 128) s_Wat[t & 7][t >> 3] = __ldg(Wa + t);
    if (tid < 64) {
        s_Wbt[tid & 7][tid >> 3] = __ldg(Wb + tid);
        s_s1b1[tid] = make_float2(__ldg(g1 + tid) * bninv, __ldg(bb1 + tid));
        s_bp2[tid]  = __ldg(bp2 + tid);
    }
    for (int t = tid; t < 192; t += 128) s_Wp2s[t / 64][t % 64] = __ldg(Wp2 + t);
    if (tid < 8) {
        s_misc[tid]      = __ldg(ba + tid);
        s_misc[8 + tid]  = __ldg(g2 + tid) * bninv;
        s_misc[16 + tid] = __ldg(bb2 + tid);
        s_misc[24 + tid] = __ldg(bw + tid);
    }
    if (tid < 9)  s_misc[32 + tid] = __ldg(Wp1 + tid);
    if (tid < 3) {
        s_misc[41 + tid] = __ldg(bp1 + tid);
        s_misc[44 + tid] = __ldg(gp + tid) * bninv;
        s_misc[47 + tid] = __ldg(bpv + tid);
    }
    __syncthreads();

    const int i0 = blockIdx.x * PTS;

    #pragma unroll 1
    for (int it = 0; it < PTS; it++) {
        const int i = i0 + it;
        const bool act = (i < N);           // uniform across block

        float val0[4], val1[4], wv[8];

        if (act) {
            const int nj = __ldg(idx + i * NS + j);
            const float rx = __ldg(p + nj * 3 + 0) - __ldg(p + i * 3 + 0);
            const float ry = __ldg(p + nj * 3 + 1) - __ldg(p + i * 3 + 1);
            const float rz = __ldg(p + nj * 3 + 2) - __ldg(p + i * 3 + 2);
            float t3[3];
            #pragma unroll
            for (int o = 0; o < 3; o++) {
                float u = fmaf(rx, s_misc[32 + o],
                          fmaf(ry, s_misc[35 + o],
                          fmaf(rz, s_misc[38 + o], s_misc[41 + o])));
                t3[o] = fmaxf(fmaf(u, s_misc[44 + o], s_misc[47 + o]), 0.f);
            }

            #pragma unroll
            for (int h = 0; h < 2; h++) {
                const int c0 = h * 32 + l * 4;
                float4 q4 = __ldg((const float4*)(g_q + (long long)i  * 64 + c0));
                float4 k4 = __ldg((const float4*)(g_k + (long long)nj * 64 + c0));
                float4 v4 = __ldg((const float4*)(g_v + (long long)nj * 64 + c0));
                float4 w0 = *(const float4*)&s_Wp2s[0][c0];
                float4 w1 = *(const float4*)&s_Wp2s[1][c0];
                float4 w2 = *(const float4*)&s_Wp2s[2][c0];
                float4 b2 = *(const float4*)&s_bp2[c0];
                float4 sb01 = *(const float4*)&s_s1b1[c0];      // {s1,b1,s1,b1}
                float4 sb23 = *(const float4*)&s_s1b1[c0 + 2];

                float pe0 = fmaf(t3[0], w0.x, fmaf(t3[1], w1.x, fmaf(t3[2], w2.x, b2.x)));
                float pe1 = fmaf(t3[0], w0.y, fmaf(t3[1], w1.y, fmaf(t3[2], w2.y, b2.y)));
                float pe2 = fmaf(t3[0], w0.z, fmaf(t3[1], w1.z, fmaf(t3[2], w2.z, b2.z)));
                float pe3 = fmaf(t3[0], w0.w, fmaf(t3[1], w1.w, fmaf(t3[2], w2.w, b2.w)));

                float* vdst = h ? val1 : val0;
                vdst[0] = v4.x + pe0; vdst[1] = v4.y + pe1;
                vdst[2] = v4.z + pe2; vdst[3] = v4.w + pe3;

                wv[h * 4 + 0] = fmaxf(fmaf(k4.x - q4.x + pe0, sb01.x, sb01.y), 0.f);
                wv[h * 4 + 1] = fmaxf(fmaf(k4.y - q4.y + pe1, sb01.z, sb01.w), 0.f);
                wv[h * 4 + 2] = fmaxf(fmaf(k4.z - q4.z + pe2, sb23.x, sb23.y), 0.f);
                wv[h * 4 + 3] = fmaxf(fmaf(k4.w - q4.w + pe3, sb23.z, sb23.w), 0.f);
            }

            // y[ch] = sum over this thread's 8 c's, then reduce across j-group
            float y[8];
            #pragma unroll
            for (int ch = 0; ch < 8; ch++) {
                float4 a0 = *(const float4*)&s_Wat[ch][l * 4];
                float4 a1 = *(const float4*)&s_Wat[ch][32 + l * 4];
                float t = 0.f;
                t = fmaf(wv[0], a0.x, t); t = fmaf(wv[1], a0.y, t);
                t = fmaf(wv[2], a0.z, t); t = fmaf(wv[3], a0.w, t);
                t = fmaf(wv[4], a1.x, t); t = fmaf(wv[5], a1.y, t);
                t = fmaf(wv[6], a1.z, t); t = fmaf(wv[7], a1.w, t);
                y[ch] = t;
            }
            #pragma unroll
            for (int off = 1; off < 8; off <<= 1) {
                #pragma unroll
                for (int ch = 0; ch < 8; ch++)
                    y[ch] += __shfl_xor_sync(0xffffffffu, y[ch], off);
            }

            // BN2 + ReLU + Wb -> score channel l
            float a[8];
            #pragma unroll
            for (int ch = 0; ch < 8; ch++)
                a[ch] = fmaxf(fmaf(y[ch] + s_misc[ch], s_misc[8 + ch], s_misc[16 + ch]), 0.f);
            float4 wb0 = *(const float4*)&s_Wbt[l][0];
            float4 wb1 = *(const float4*)&s_Wbt[l][4];
            float sc = s_misc[24 + l];
            sc = fmaf(a[0], wb0.x, sc); sc = fmaf(a[1], wb0.y, sc);
            sc = fmaf(a[2], wb0.z, sc); sc = fmaf(a[3], wb0.w, sc);
            sc = fmaf(a[4], wb1.x, sc); sc = fmaf(a[5], wb1.y, sc);
            sc = fmaf(a[6], wb1.z, sc); sc = fmaf(a[7], wb1.w, sc);
            s_wraw[j][l] = sc;
        }
        __syncthreads();

        if (act && tid < 8) {
            float mx = -1e30f;
            #pragma unroll
            for (int jj = 0; jj < NS; jj++) mx = fmaxf(mx, s_wraw[jj][tid]);
            float sm = 0.f;
            #pragma unroll
            for (int jj = 0; jj < NS; jj++) sm += __expf(s_wraw[jj][tid] - mx);
            float inv = 1.f / sm;
            #pragma unroll
            for (int jj = 0; jj < NS; jj++)
                s_w[jj][tid] = __expf(s_wraw[jj][tid] - mx) * inv;
        }
        __syncthreads();

        if (act) {
            // apply weights to register vals; channel c uses w[j][c & 7]
            float4 w4 = *(const float4*)&s_w[j][(l & 1) * 4];
            float c0[4], c1[4];
            c0[0] = val0[0] * w4.x; c0[1] = val0[1] * w4.y;
            c0[2] = val0[2] * w4.z; c0[3] = val0[3] * w4.w;
            c1[0] = val1[0] * w4.x; c1[1] = val1[1] * w4.y;
            c1[2] = val1[2] * w4.z; c1[3] = val1[3] * w4.w;
            // reduce over the 4 in-warp neighbors (lane bits 3,4)
            #pragma unroll
            for (int off = 8; off <= 16; off <<= 1) {
                #pragma unroll
                for (int q = 0; q < 4; q++) {
                    c0[q] += __shfl_xor_sync(0xffffffffu, c0[q], off);
                    c1[q] += __shfl_xor_sync(0xffffffffu, c1[q], off);
                }
            }
            if ((tid & 24) == 0) {    // one lane per (warp, l)
                *(float4*)&s_part[wid][l * 4]      = make_float4(c0[0], c0[1], c0[2], c0[3]);
                *(float4*)&s_part[wid][32 + l * 4] = make_float4(c1[0], c1[1], c1[2], c1[3]);
            }
        }
        __syncthreads();

        if (act && tid < 64) {
            float o = s_part[0][tid] + s_part[1][tid] + s_part[2][tid] + s_part[3][tid];
            out[(long long)i * 64 + tid] = o;
        }
    }
}

// ---------------------------------------------------------------------------
extern "C" void kernel_launch(void* const* d_in, const int* in_sizes, int n_in,
                              void* d_out, int out_size)
{
    const float* p   = (const float*)d_in[0];
    const float* x   = (const float*)d_in[1];
    const int*   idx = (const int*)  d_in[2];
    const float* Wq  = (const float*)d_in[3];
    const float* bq  = (const float*)d_in[4];
    const float* Wk  = (const float*)d_in[5];
    const float* bk  = (const float*)d_in[6];
    const float* Wv  = (const float*)d_in[7];
    const float* bv  = (const float*)d_in[8];
    const float* Wp1 = (const float*)d_in[9];
    const float* bp1 = (const float*)d_in[10];
    const float* gp  = (const float*)d_in[11];
    const float* bpv = (const float*)d_in[12];
    const float* Wp2 = (const float*)d_in[13];
    const float* bp2 = (const float*)d_in[14];
    const float* g1  = (const float*)d_in[15];
    const float* bb1 = (const float*)d_in[16];
    const float* Wa  = (const float*)d_in[17];
    const float* ba  = (const float*)d_in[18];
    const float* g2  = (const float*)d_in[19];
    const float* bb2 = (const float*)d_in[20];
    const float* Wb  = (const float*)d_in[21];
    const float* bw  = (const float*)d_in[22];
    float* out = (float*)d_out;

    int N = in_sizes[1] / C;
    if (N > MAXN) N = MAXN;

    qkv_gemm<<<(N + QROWS - 1) / QROWS, 128>>>(x, Wq, bq, Wk, bk, Wv, bv, N);

    pt_attn<<<(N + PTS - 1) / PTS, 128>>>(p, idx, Wp1, bp1, gp, bpv, Wp2, bp2,
                                          g1, bb1, Wa, ba, g2, bb2, Wb, bw, out, N);
}